// round 9
// baseline (speedup 1.0000x reference)
#include <cuda_runtime.h>
#include <cuda_bf16.h>
#include <math.h>
#include <stdint.h>

#define NTOK   32768
#define CDIM   256
#define SCODE  1024
#define HW     1024
#define BETA   0.25f

// certified bounds: |w| <= 2^-10, |w - bf16(w)| <= 2^-9 * 2^-10 = 2^-19
#define WMAX   9.765625e-4f
#define WLOMAX 1.9073486e-6f

// ======================= device scratch ====================================
__device__ float          g_w2[SCODE];
__device__ float          g_x2[NTOK];
__device__ float          g_marg[NTOK];
__device__ int            g_idx[NTOK];
__device__ unsigned int   g_hist[SCODE];
__device__ float          g_losspart[512];
__device__ __nv_bfloat16  g_xhi[NTOK * CDIM];   // [tok][k]
__device__ __nv_bfloat16  g_ehi[SCODE * CDIM];  // [code][k]
__device__ int            g_cand[NTOK * 16];    // two half-lists of 8
__device__ int            g_cnt [NTOK * 2];

// ======================= small helpers =====================================
__device__ __forceinline__ uint32_t smem_u32(const void* p) {
    uint32_t a;
    asm("{ .reg .u64 t; cvta.to.shared.u64 t, %1; cvt.u32.u64 %0, t; }" : "=r"(a) : "l"(p));
    return a;
}
__device__ __forceinline__ void ldsm4(uint32_t& r0, uint32_t& r1, uint32_t& r2, uint32_t& r3,
                                      uint32_t addr) {
    asm volatile("ldmatrix.sync.aligned.m8n8.x4.shared.b16 {%0,%1,%2,%3}, [%4];"
                 : "=r"(r0), "=r"(r1), "=r"(r2), "=r"(r3) : "r"(addr));
}
__device__ __forceinline__ void mma16816(float* c, const uint32_t* a, uint32_t b0, uint32_t b1) {
    asm volatile("mma.sync.aligned.m16n8k16.row.col.f32.bf16.bf16.f32 "
                 "{%0,%1,%2,%3}, {%4,%5,%6,%7}, {%8,%9}, {%0,%1,%2,%3};"
                 : "+f"(c[0]), "+f"(c[1]), "+f"(c[2]), "+f"(c[3])
                 : "r"(a[0]), "r"(a[1]), "r"(a[2]), "r"(a[3]), "r"(b0), "r"(b1));
}
// swizzled byte offset in a [row][256 bf16] tile (512B rows, 16B granules)
__device__ __forceinline__ uint32_t swz(int row, int k) {   // k multiple of 8
    int ch = k >> 3;   // 0..31
    return (uint32_t)(row * 512 + ((ch >> 3) << 7) + (((ch & 7) ^ (row & 7)) << 4));
}

// ======================= kernel 0: w2 exact + zero scratch ==================
__global__ void k_init(const float* __restrict__ emb) {
    int t = blockIdx.x * 256 + threadIdx.x;   // 0..1023
    const float* row = emb + (size_t)t * CDIM;
    float s = 0.f;
    for (int k = 0; k < CDIM; k++) s = __fadd_rn(s, __fmul_rn(row[k], row[k]));
    g_w2[t] = s;
    g_hist[t] = 0u;
    if (t < 512) g_losspart[t] = 0.f;
}

// ======================= kernel: transpose x -> bf16 hi ====================
__global__ void k_pre(const float* __restrict__ x) {
    __shared__ float tile[32][33];
    int b = blockIdx.z, c0 = blockIdx.y * 32, hw0 = blockIdx.x * 32;
    int tx = threadIdx.x, ty = threadIdx.y;
    const float* xb = x + ((size_t)b * CDIM + c0) * HW + hw0;
#pragma unroll
    for (int r = 0; r < 4; r++)
        tile[ty + r * 8][tx] = xb[(size_t)(ty + r * 8) * HW + tx];
    __syncthreads();
    int nb = b * HW + hw0;
#pragma unroll
    for (int r = 0; r < 4; r++) {
        int hwl = ty + r * 8;
        float v = tile[tx][hwl];
        g_xhi[(size_t)(nb + hwl) * CDIM + c0 + tx] = __float2bfloat16(v);
    }
}

// ======================= kernel: exact x2 + certified margin ===============
__global__ void k_x2(const float* __restrict__ x) {
    int n = blockIdx.x * 256 + threadIdx.x;
    int b = n >> 10, hw = n & 1023;
    const float* p = x + (size_t)b * CDIM * HW + hw;
    float s = 0.f, sa = 0.f, sh = 0.f;
    for (int c = 0; c < CDIM; c++) {
        float v = p[(size_t)c * HW];
        s = __fadd_rn(s, __fmul_rn(v, v));          // reference chain for x2
        float hv = __bfloat162float(__float2bfloat16(v));
        sh += fabsf(hv);
        sa += fabsf(v - hv);
    }
    g_x2[n] = s;
    float g = __uint_as_float(__float_as_uint(s + 0.25f) & 0x7f800000u) * 1.1920929e-7f; // ulp
    g_marg[n] = 2.f * g + 2.f * (WMAX * sa + WLOMAX * sh) + 1e-5f;
}

// ======================= kernel: emb bf16 hi ================================
__global__ void k_esplit(const float* __restrict__ emb) {
    int i = blockIdx.x * 256 + threadIdx.x;   // < 262144
    g_ehi[i] = __float2bfloat16(emb[i]);
}

// ======================= kernel: HMMA score + candidate filter =============
// 256 blocks x 256 threads (8 warps); 128 tokens/block; 16 code tiles of 64.
#define SA    0
#define SB0   65536
#define SB1   98304
#define SW2   131072
#define SEPI  135168          // 8 warps * 16*68*4 = 34816
#define SMEM_SZ (135168 + 34816)

__global__ void __launch_bounds__(256, 1) k_mma() {
    extern __shared__ char smem[];
    const uint32_t sb = smem_u32(smem);
    const int tid  = threadIdx.x;
    const int wid  = tid >> 5;
    const int lane = tid & 31;
    const int n0   = blockIdx.x * 128;
    const int tw   = wid * 16;                    // warp's token base within block
    float* w2s = (float*)(smem + SW2);
    float* epi = (float*)(smem + SEPI) + wid * 16 * 68;

    // load A (x_hi 128x256 bf16, swizzled)
#pragma unroll
    for (int i = 0; i < 16; i++) {
        int v = i * 256 + tid;                    // 0..4095
        int row = v >> 5, ch = v & 31;
        uint4 d = *(const uint4*)(g_xhi + (size_t)(n0 + row) * CDIM + ch * 8);
        *(uint4*)(smem + SA + swz(row, ch * 8)) = d;
    }
    // load B tile 0
#pragma unroll
    for (int i = 0; i < 8; i++) {
        int v = i * 256 + tid;                    // 0..2047
        int row = v >> 5, ch = v & 31;
        uint4 d = *(const uint4*)(g_ehi + (size_t)row * CDIM + ch * 8);
        *(uint4*)(smem + SB0 + swz(row, ch * 8)) = d;
    }
    // w2 -> smem
#pragma unroll
    for (int i = 0; i < 4; i++) w2s[tid + i * 256] = g_w2[tid + i * 256];
    __syncthreads();

    // per-lane scan state: token r = lane&15, half h = lane>>4 (cols h*32..+31)
    const int rtok = lane & 15;
    const int half = lane >> 4;
    float locmin = 3.4e38f;
    float marg = g_marg[n0 + tw + rtok];
    int cand[8]; int cnt = 0; bool ovf = false;

    // ldmatrix lane addressing (constant per lane)
    const int arow = tw + (lane & 15);
    const int akof = (lane >> 4) << 3;
    const int brow = (lane & 7) + ((lane >> 4) << 3);   // + g*16
    const int bkof = ((lane >> 3) & 1) << 3;

    for (int t = 0; t < 16; t++) {
        char* B = smem + ((t & 1) ? SB1 : SB0);
        // stage next B tile into registers (hidden under compute)
        uint4 st[8];
        if (t < 15) {
#pragma unroll
            for (int i = 0; i < 8; i++) {
                int v = i * 256 + tid;
                int row = v >> 5, ch = v & 31;
                st[i] = *(const uint4*)(g_ehi + (size_t)((t + 1) * 64 + row) * CDIM + ch * 8);
            }
        }

        float acc[8][4];
#pragma unroll
        for (int g = 0; g < 8; g++)
#pragma unroll
            for (int j = 0; j < 4; j++) acc[g][j] = 0.f;

#pragma unroll
        for (int ks = 0; ks < 16; ks++) {
            uint32_t a[4];
            ldsm4(a[0], a[1], a[2], a[3], sb + SA + swz(arow, ks * 16 + akof));
#pragma unroll
            for (int g = 0; g < 4; g++) {
                uint32_t b0, b1, b2, b3;
                ldsm4(b0, b1, b2, b3,
                      sb + (uint32_t)(B - smem) + swz(g * 16 + brow, ks * 16 + bkof));
                mma16816(acc[2 * g],     a, b0, b1);
                mma16816(acc[2 * g + 1], a, b2, b3);
            }
        }

        // epilogue: s = w2 - 2*dot -> per-warp smem, then scan
        {
            const int cb = t * 64;
            const int r4  = lane >> 2;          // row 0..7
            const int c2  = (lane & 3) * 2;
#pragma unroll
            for (int g = 0; g < 8; g++) {
                int col = g * 8 + c2;
                float2 v0, v1;
                v0.x = w2s[cb + col]     - 2.f * acc[g][0];
                v0.y = w2s[cb + col + 1] - 2.f * acc[g][1];
                v1.x = w2s[cb + col]     - 2.f * acc[g][2];
                v1.y = w2s[cb + col + 1] - 2.f * acc[g][3];
                *(float2*)(epi + r4 * 68 + col)       = v0;
                *(float2*)(epi + (r4 + 8) * 68 + col) = v1;
            }
        }
        __syncwarp();
#pragma unroll 4
        for (int c = 0; c < 32; c++) {
            float v = epi[rtok * 68 + half * 32 + c];
            if (v < locmin + marg) {
                if (cnt < 8) cand[cnt++] = t * 64 + half * 32 + c; else ovf = true;
                if (v < locmin) locmin = v;
            }
        }
        __syncwarp();

        // commit staged B, barrier
        if (t < 15) {
            char* Bn = smem + ((t & 1) ? SB0 : SB1);
#pragma unroll
            for (int i = 0; i < 8; i++) {
                int v = i * 256 + tid;
                int row = v >> 5, ch = v & 31;
                *(uint4*)(Bn + swz(row, ch * 8)) = st[i];
            }
        }
        __syncthreads();
    }

    const int tokg = n0 + tw + rtok;
    g_cnt[tokg * 2 + half] = ovf ? 100 : cnt;
#pragma unroll
    for (int i = 0; i < 8; i++)
        if (i < cnt) g_cand[(size_t)tokg * 16 + half * 8 + i] = cand[i];
}

// ======================= kernel: exact recompute on candidates =============
__global__ void k_exact(const float* __restrict__ x, const float* __restrict__ emb) {
    int n = blockIdx.x * 256 + threadIdx.x;
    int b = n >> 10, hw = n & 1023;
    const float* xp = x + (size_t)b * CDIM * HW + hw;
    float x2 = g_x2[n];
    int c0 = g_cnt[n * 2], c1 = g_cnt[n * 2 + 1];
    float best = 3.4e38f; int bi = SCODE;

    if (c0 <= 8 && c1 <= 8) {
        int m = c0 + c1;
        int cs[16];
        for (int i = 0; i < c0; i++) cs[i] = g_cand[(size_t)n * 16 + i];
        for (int i = 0; i < c1; i++) cs[c0 + i] = g_cand[(size_t)n * 16 + 8 + i];
        float dots[16];
        for (int i = 0; i < m; i++) dots[i] = 0.f;
        for (int kc = 0; kc < CDIM; kc += 32) {
            float xr[32];
#pragma unroll
            for (int k = 0; k < 32; k++) xr[k] = xp[(size_t)(kc + k) * HW];
            for (int i = 0; i < m; i++) {
                const float* e = emb + (size_t)cs[i] * CDIM + kc;
                float d = dots[i];
#pragma unroll
                for (int k = 0; k < 32; k++) d = fmaf(xr[k], e[k], d);
                dots[i] = d;
            }
        }
        for (int i = 0; i < m; i++) {
            int s = cs[i];
            float q = __fadd_rn(__fadd_rn(x2, -__fmul_rn(2.f, dots[i])), g_w2[s]);
            if (q < best || (q == best && s < bi)) { best = q; bi = s; }
        }
    } else {
        // fallback: full exact scan (expected never)
        for (int s = 0; s < SCODE; s++) {
            const float* e = emb + (size_t)s * CDIM;
            float dot = 0.f;
            for (int k = 0; k < CDIM; k++) dot = fmaf(xp[(size_t)k * HW], e[k], dot);
            float q = __fadd_rn(__fadd_rn(x2, -__fmul_rn(2.f, dot)), g_w2[s]);
            if (q < best) { best = q; bi = s; }
        }
    }
    g_idx[n] = bi;
    atomicAdd(&g_hist[bi], 1u);
}

// ======================= kernel: gather + ST write + loss ==================
__global__ void k_gather(const float* __restrict__ x, const float* __restrict__ emb,
                         float* __restrict__ out) {
    const int n0  = blockIdx.x * 64;
    const int b   = n0 >> 10;
    const int hw0 = n0 & 1023;
    const int tok = threadIdx.x & 63;
    const int cc  = threadIdx.x >> 6;

    const int mi = g_idx[n0 + tok];
    const float* e = emb + (size_t)mi * CDIM;
    const size_t base = (size_t)b * (CDIM * HW) + hw0 + tok;

    float s = 0.f;
    for (int c = cc; c < CDIM; c += 4) {
        float v = __ldg(e + c);
        size_t off = base + (size_t)c * HW;
        float xv = x[off];
        float diff = __fadd_rn(v, -xv);
        out[off] = __fadd_rn(xv, diff);
        s = fmaf(diff, diff, s);
    }
    __shared__ float red[256];
    red[threadIdx.x] = s;
    __syncthreads();
    for (int st = 128; st > 0; st >>= 1) {
        if (threadIdx.x < st) red[threadIdx.x] += red[threadIdx.x + st];
        __syncthreads();
    }
    if (threadIdx.x == 0) g_losspart[blockIdx.x] = red[0];
}

// ======================= kernel: finalize ==================================
__global__ void k_final(float* __restrict__ out, int out_size) {
    __shared__ float red[1024];
    const int t = threadIdx.x;
    float p = (float)g_hist[t] / (float)NTOK;
    red[t] = p * logf(p + 1e-6f);
    __syncthreads();
    for (int st = 512; st > 0; st >>= 1) {
        if (t < st) red[t] += red[t + st];
        __syncthreads();
    }
    float plogp = red[0];
    __syncthreads();
    red[t] = (t < 512) ? g_losspart[t] : 0.f;
    __syncthreads();
    for (int st = 512; st > 0; st >>= 1) {
        if (t < st) red[t] += red[t + st];
        __syncthreads();
    }
    if (t == 0) {
        out[out_size - 2] = BETA * (red[0] / (float)(NTOK * CDIM));
        out[out_size - 1] = expf(-plogp);
    }
}

// ======================= launch ============================================
extern "C" void kernel_launch(void* const* d_in, const int* in_sizes, int n_in,
                              void* d_out, int out_size) {
    const float* x   = (const float*)d_in[0];   // [32,256,32,32]
    const float* emb = (const float*)d_in[1];   // [1024,256]
    float* out = (float*)d_out;

    k_init<<<4, 256>>>(emb);
    k_pre<<<dim3(32, 8, 32), dim3(32, 8)>>>(x);
    k_x2<<<NTOK / 256, 256>>>(x);
    k_esplit<<<SCODE * CDIM / 256, 256>>>(emb);

    cudaFuncSetAttribute(k_mma, cudaFuncAttributeMaxDynamicSharedMemorySize, SMEM_SZ);
    k_mma<<<NTOK / 128, 256, SMEM_SZ>>>();

    k_exact<<<NTOK / 256, 256>>>(x, emb);
    k_gather<<<NTOK / 64, 256>>>(x, emb, out);
    k_final<<<1, 1024>>>(out, out_size);
}

// round 10
// speedup vs baseline: 18.1988x; 18.1988x over previous
#include <cuda_runtime.h>
#include <cuda_bf16.h>
#include <math.h>
#include <stdint.h>

#define NTOK   32768
#define CDIM   256
#define SCODE  1024
#define HW     1024
#define BETA   0.25f

// certified bounds: |w| <= 2^-10, |w - bf16(w)| <= 2^-9 * 2^-10 = 2^-19
#define WMAX   9.765625e-4f
#define WLOMAX 1.9073486e-6f

// ======================= device scratch ====================================
__device__ float          g_w2[SCODE];
__device__ float          g_x2[NTOK];
__device__ float          g_marg[NTOK];
__device__ int            g_idx[NTOK];
__device__ unsigned int   g_hist[SCODE];
__device__ float          g_losspart[512];
__device__ __nv_bfloat16  g_xhi[NTOK * CDIM];   // [tok][k]
__device__ __nv_bfloat16  g_ehi[SCODE * CDIM];  // [code][k]
__device__ float          g_scores[(size_t)NTOK * SCODE];   // 128 MB
__device__ int            g_cand[NTOK * 16];
__device__ int            g_cnt [NTOK];

// ======================= small helpers =====================================
__device__ __forceinline__ uint32_t smem_u32(const void* p) {
    uint32_t a;
    asm("{ .reg .u64 t; cvta.to.shared.u64 t, %1; cvt.u32.u64 %0, t; }" : "=r"(a) : "l"(p));
    return a;
}
__device__ __forceinline__ void ldsm4(uint32_t& r0, uint32_t& r1, uint32_t& r2, uint32_t& r3,
                                      uint32_t addr) {
    asm volatile("ldmatrix.sync.aligned.m8n8.x4.shared.b16 {%0,%1,%2,%3}, [%4];"
                 : "=r"(r0), "=r"(r1), "=r"(r2), "=r"(r3) : "r"(addr));
}
__device__ __forceinline__ void mma16816(float* c, const uint32_t* a, uint32_t b0, uint32_t b1) {
    asm volatile("mma.sync.aligned.m16n8k16.row.col.f32.bf16.bf16.f32 "
                 "{%0,%1,%2,%3}, {%4,%5,%6,%7}, {%8,%9}, {%0,%1,%2,%3};"
                 : "+f"(c[0]), "+f"(c[1]), "+f"(c[2]), "+f"(c[3])
                 : "r"(a[0]), "r"(a[1]), "r"(a[2]), "r"(a[3]), "r"(b0), "r"(b1));
}
// swizzled byte offset in a [row][256 bf16] tile (512B rows, 16B granules)
__device__ __forceinline__ uint32_t swz(int row, int k) {   // k multiple of 8
    int ch = k >> 3;   // 0..31
    return (uint32_t)(row * 512 + ((ch >> 3) << 7) + (((ch & 7) ^ (row & 7)) << 4));
}

// ======================= kernel 0: w2 exact + zero scratch ==================
__global__ void k_init(const float* __restrict__ emb) {
    int t = blockIdx.x * 256 + threadIdx.x;   // 0..1023
    const float* row = emb + (size_t)t * CDIM;
    float s = 0.f;
    for (int k = 0; k < CDIM; k++) s = __fadd_rn(s, __fmul_rn(row[k], row[k]));
    g_w2[t] = s;
    g_hist[t] = 0u;
    if (t < 512) g_losspart[t] = 0.f;
}

// ======================= kernel: transpose x -> bf16 hi ====================
__global__ void k_pre(const float* __restrict__ x) {
    __shared__ float tile[32][33];
    int b = blockIdx.z, c0 = blockIdx.y * 32, hw0 = blockIdx.x * 32;
    int tx = threadIdx.x, ty = threadIdx.y;
    const float* xb = x + ((size_t)b * CDIM + c0) * HW + hw0;
#pragma unroll
    for (int r = 0; r < 4; r++)
        tile[ty + r * 8][tx] = xb[(size_t)(ty + r * 8) * HW + tx];
    __syncthreads();
    int nb = b * HW + hw0;
#pragma unroll
    for (int r = 0; r < 4; r++) {
        int hwl = ty + r * 8;
        float v = tile[tx][hwl];
        g_xhi[(size_t)(nb + hwl) * CDIM + c0 + tx] = __float2bfloat16(v);
    }
}

// ======================= kernel: exact x2 + certified margin ===============
__global__ void k_x2(const float* __restrict__ x) {
    int n = blockIdx.x * 256 + threadIdx.x;
    int b = n >> 10, hw = n & 1023;
    const float* p = x + (size_t)b * CDIM * HW + hw;
    float s = 0.f, sa = 0.f, sh = 0.f;
    for (int c = 0; c < CDIM; c++) {
        float v = p[(size_t)c * HW];
        s = __fadd_rn(s, __fmul_rn(v, v));          // reference chain for x2
        float hv = __bfloat162float(__float2bfloat16(v));
        sh += fabsf(hv);
        sa += fabsf(v - hv);
    }
    g_x2[n] = s;
    float g = __uint_as_float(__float_as_uint(s + 0.25f) & 0x7f800000u) * 1.1920929e-7f; // ulp
    g_marg[n] = 2.f * g + 2.f * (WMAX * sa + WLOMAX * sh) + 1e-5f;
}

// ======================= kernel: emb bf16 hi ================================
__global__ void k_esplit(const float* __restrict__ emb) {
    int i = blockIdx.x * 256 + threadIdx.x;   // < 262144
    g_ehi[i] = __float2bfloat16(emb[i]);
}

// ======================= kernel: HMMA score GEMM ===========================
// 256 blocks x 256 threads (8 warps); 128 tokens/block; 16 code tiles of 64.
#define SA    0
#define SB0   65536
#define SB1   98304
#define SW2   131072
#define SMEM_SZ 135168

__global__ void __launch_bounds__(256, 1) k_mma() {
    extern __shared__ char smem[];
    const uint32_t sb = smem_u32(smem);
    const int tid  = threadIdx.x;
    const int wid  = tid >> 5;
    const int lane = tid & 31;
    const int n0   = blockIdx.x * 128;
    const int tw   = wid * 16;                    // warp's token base within block
    float* w2s = (float*)(smem + SW2);

    // load A (x_hi 128x256 bf16, swizzled)
#pragma unroll
    for (int i = 0; i < 16; i++) {
        int v = i * 256 + tid;                    // 0..4095
        int row = v >> 5, ch = v & 31;
        uint4 d = *(const uint4*)(g_xhi + (size_t)(n0 + row) * CDIM + ch * 8);
        *(uint4*)(smem + SA + swz(row, ch * 8)) = d;
    }
    // load B tile 0
#pragma unroll
    for (int i = 0; i < 8; i++) {
        int v = i * 256 + tid;                    // 0..2047
        int row = v >> 5, ch = v & 31;
        uint4 d = *(const uint4*)(g_ehi + (size_t)row * CDIM + ch * 8);
        *(uint4*)(smem + SB0 + swz(row, ch * 8)) = d;
    }
    // w2 -> smem
#pragma unroll
    for (int i = 0; i < 4; i++) w2s[tid + i * 256] = g_w2[tid + i * 256];
    __syncthreads();

    // ldmatrix lane addressing (constant per lane)
    const int arow = tw + (lane & 15);
    const int akof = (lane >> 4) << 3;
    const int brow = (lane & 7) + ((lane >> 4) << 3);   // + g*16
    const int bkof = ((lane >> 3) & 1) << 3;

    // epilogue addressing
    const int r4 = lane >> 2;            // 0..7
    const int c2 = (lane & 3) * 2;

    for (int t = 0; t < 16; t++) {
        char* B = smem + ((t & 1) ? SB1 : SB0);
        // stage next B tile into registers (hidden under compute)
        uint4 st[8];
        if (t < 15) {
#pragma unroll
            for (int i = 0; i < 8; i++) {
                int v = i * 256 + tid;
                int row = v >> 5, ch = v & 31;
                st[i] = *(const uint4*)(g_ehi + (size_t)((t + 1) * 64 + row) * CDIM + ch * 8);
            }
        }

        float acc[8][4];
#pragma unroll
        for (int g = 0; g < 8; g++)
#pragma unroll
            for (int j = 0; j < 4; j++) acc[g][j] = 0.f;

#pragma unroll
        for (int ks = 0; ks < 16; ks++) {
            uint32_t a[4];
            ldsm4(a[0], a[1], a[2], a[3], sb + SA + swz(arow, ks * 16 + akof));
#pragma unroll
            for (int g = 0; g < 4; g++) {
                uint32_t b0, b1, b2, b3;
                ldsm4(b0, b1, b2, b3,
                      sb + (uint32_t)(B - smem) + swz(g * 16 + brow, ks * 16 + bkof));
                mma16816(acc[2 * g],     a, b0, b1);
                mma16816(acc[2 * g + 1], a, b2, b3);
            }
        }

        // epilogue: s = w2 - 2*dot -> gmem score matrix (coalesced float2)
        {
            const int cb = t * 64;
            float* s0 = g_scores + (size_t)(n0 + tw + r4) * SCODE + cb;
            float* s1 = g_scores + (size_t)(n0 + tw + r4 + 8) * SCODE + cb;
#pragma unroll
            for (int g = 0; g < 8; g++) {
                int col = g * 8 + c2;
                float w0 = w2s[cb + col], w1 = w2s[cb + col + 1];
                float2 v0 = { w0 - 2.f * acc[g][0], w1 - 2.f * acc[g][1] };
                float2 v1 = { w0 - 2.f * acc[g][2], w1 - 2.f * acc[g][3] };
                *(float2*)(s0 + col) = v0;
                *(float2*)(s1 + col) = v1;
            }
        }

        // commit staged B, barrier
        if (t < 15) {
            char* Bn = smem + ((t & 1) ? SB0 : SB1);
#pragma unroll
            for (int i = 0; i < 8; i++) {
                int v = i * 256 + tid;
                int row = v >> 5, ch = v & 31;
                *(uint4*)(Bn + swz(row, ch * 8)) = st[i];
            }
            __syncthreads();
        }
    }
}

// ======================= kernel: min + candidate collection ================
// one warp per token; 1024 scores held in 32 regs/lane; final-min filter
__global__ void k_scan() {
    const int wid = threadIdx.x >> 5, lane = threadIdx.x & 31;
    const int n = blockIdx.x * 8 + wid;
    const float* s = g_scores + (size_t)n * SCODE;

    float v[32];
    float mn = 3.4e38f;
#pragma unroll
    for (int i = 0; i < 32; i++) {
        v[i] = s[lane + i * 32];
        mn = fminf(mn, v[i]);
    }
#pragma unroll
    for (int o = 16; o > 0; o >>= 1) mn = fminf(mn, __shfl_xor_sync(~0u, mn, o));

    const float thr = mn + g_marg[n];
    __shared__ int scnt[8];
    if (lane == 0) scnt[wid] = 0;
    __syncwarp();
    int ovf = 0;
#pragma unroll
    for (int i = 0; i < 32; i++) {
        if (v[i] < thr) {
            int pos = atomicAdd(&scnt[wid], 1);
            if (pos < 16) g_cand[(size_t)n * 16 + pos] = lane + i * 32;
            else ovf = 1;
        }
    }
    __syncwarp();
    ovf = __any_sync(~0u, ovf);
    if (lane == 0) g_cnt[n] = ovf ? 1000 : scnt[wid];
}

// ======================= kernel: exact recompute on candidates =============
__global__ void k_exact(const float* __restrict__ x, const float* __restrict__ emb) {
    int n = blockIdx.x * 256 + threadIdx.x;
    int b = n >> 10, hw = n & 1023;
    const float* xp = x + (size_t)b * CDIM * HW + hw;
    float x2 = g_x2[n];
    int cnt = g_cnt[n];
    float best = 3.4e38f; int bi = SCODE;

    if (cnt <= 16) {
        int cs[16];
        for (int i = 0; i < cnt; i++) cs[i] = g_cand[(size_t)n * 16 + i];
        float dots[16];
        for (int i = 0; i < cnt; i++) dots[i] = 0.f;
        for (int kc = 0; kc < CDIM; kc += 32) {
            float xr[32];
#pragma unroll
            for (int k = 0; k < 32; k++) xr[k] = xp[(size_t)(kc + k) * HW];
            for (int i = 0; i < cnt; i++) {
                const float* e = emb + (size_t)cs[i] * CDIM + kc;
                float d = dots[i];
#pragma unroll
                for (int k = 0; k < 32; k++) d = fmaf(xr[k], e[k], d);
                dots[i] = d;
            }
        }
        for (int i = 0; i < cnt; i++) {
            int ss = cs[i];
            float q = __fadd_rn(__fadd_rn(x2, -__fmul_rn(2.f, dots[i])), g_w2[ss]);
            if (q < best || (q == best && ss < bi)) { best = q; bi = ss; }
        }
    } else {
        // fallback: full exact scan (expected never)
        for (int ss = 0; ss < SCODE; ss++) {
            const float* e = emb + (size_t)ss * CDIM;
            float dot = 0.f;
            for (int k = 0; k < CDIM; k++) dot = fmaf(xp[(size_t)k * HW], e[k], dot);
            float q = __fadd_rn(__fadd_rn(x2, -__fmul_rn(2.f, dot)), g_w2[ss]);
            if (q < best) { best = q; bi = ss; }
        }
    }
    g_idx[n] = bi;
    atomicAdd(&g_hist[bi], 1u);
}

// ======================= kernel: gather + ST write + loss ==================
__global__ void k_gather(const float* __restrict__ x, const float* __restrict__ emb,
                         float* __restrict__ out) {
    const int n0  = blockIdx.x * 64;
    const int b   = n0 >> 10;
    const int hw0 = n0 & 1023;
    const int tok = threadIdx.x & 63;
    const int cc  = threadIdx.x >> 6;

    const int mi = g_idx[n0 + tok];
    const float* e = emb + (size_t)mi * CDIM;
    const size_t base = (size_t)b * (CDIM * HW) + hw0 + tok;

    float s = 0.f;
    for (int c = cc; c < CDIM; c += 4) {
        float v = __ldg(e + c);
        size_t off = base + (size_t)c * HW;
        float xv = x[off];
        float diff = __fadd_rn(v, -xv);
        out[off] = __fadd_rn(xv, diff);
        s = fmaf(diff, diff, s);
    }
    __shared__ float red[256];
    red[threadIdx.x] = s;
    __syncthreads();
    for (int st = 128; st > 0; st >>= 1) {
        if (threadIdx.x < st) red[threadIdx.x] += red[threadIdx.x + st];
        __syncthreads();
    }
    if (threadIdx.x == 0) g_losspart[blockIdx.x] = red[0];
}

// ======================= kernel: finalize ==================================
__global__ void k_final(float* __restrict__ out, int out_size) {
    __shared__ float red[1024];
    const int t = threadIdx.x;
    float p = (float)g_hist[t] / (float)NTOK;
    red[t] = p * logf(p + 1e-6f);
    __syncthreads();
    for (int st = 512; st > 0; st >>= 1) {
        if (t < st) red[t] += red[t + st];
        __syncthreads();
    }
    float plogp = red[0];
    __syncthreads();
    red[t] = (t < 512) ? g_losspart[t] : 0.f;
    __syncthreads();
    for (int st = 512; st > 0; st >>= 1) {
        if (t < st) red[t] += red[t + st];
        __syncthreads();
    }
    if (t == 0) {
        out[out_size - 2] = BETA * (red[0] / (float)(NTOK * CDIM));
        out[out_size - 1] = expf(-plogp);
    }
}

// ======================= launch ============================================
extern "C" void kernel_launch(void* const* d_in, const int* in_sizes, int n_in,
                              void* d_out, int out_size) {
    const float* x   = (const float*)d_in[0];   // [32,256,32,32]
    const float* emb = (const float*)d_in[1];   // [1024,256]
    float* out = (float*)d_out;

    k_init<<<4, 256>>>(emb);
    k_pre<<<dim3(32, 8, 32), dim3(32, 8)>>>(x);
    k_x2<<<NTOK / 256, 256>>>(x);
    k_esplit<<<SCODE * CDIM / 256, 256>>>(emb);

    cudaFuncSetAttribute(k_mma, cudaFuncAttributeMaxDynamicSharedMemorySize, SMEM_SZ);
    k_mma<<<NTOK / 128, 256, SMEM_SZ>>>();

    k_scan<<<NTOK / 8, 256>>>();
    k_exact<<<NTOK / 256, 256>>>(x, emb);
    k_gather<<<NTOK / 64, 256>>>(x, emb, out);
    k_final<<<1, 1024>>>(out, out_size);
}